// round 7
// baseline (speedup 1.0000x reference)
#include <cuda_runtime.h>
#include <math.h>

#define NB 32
#define NA 8400
#define NM 50
#define NC 80
#define KTOP 10
#define PRED_DIM 85
#define MAXF 2048
#define BMW 263
#define INPUT_SZ 640.0f
#define PI_F 3.14159265358979323846f

// ---------------- scratch ----------------
__device__ int      g_nf[NB];
__device__ int      g_flist[NB*MAXF];
__device__ int      g_cidx[NB*NA];
__device__ unsigned g_bitmap[NB*BMW];
__device__ float    g_cls[NB*MAXF*NC];        // cls_cost term, [b][slot][c]
__device__ float4   g_boxc[NB*MAXF];
__device__ float    g_costc[NB*NM*MAXF];      // dup resolution only
__device__ int      g_amg[NB*NA];             // (count<<16) | sum_of_m
__device__ float    g_acc[NB*4];

// ---------------- helpers ----------------
__device__ __forceinline__ void anchor_geom(int a, float& xc, float& yc, float& cd){
    if (a < 6400){
        int y = a / 80, x = a - y*80;
        xc = (x + 0.5f)*8.f;  yc = (y + 0.5f)*8.f;  cd = 12.f;
    } else if (a < 8000){
        int i = a - 6400; int y = i / 40, x = i - y*40;
        xc = (x + 0.5f)*16.f; yc = (y + 0.5f)*16.f; cd = 24.f;
    } else {
        int i = a - 8000; int y = i / 20, x = i - y*20;
        xc = (x + 0.5f)*32.f; yc = (y + 0.5f)*32.f; cd = 48.f;
    }
}

__device__ __forceinline__ float sigmoid_f(float x){
    return 1.f / (1.f + __expf(-x));
}

__device__ __forceinline__ float bce_logits(float x, float t){
    return fmaxf(x, 0.f) - x*t + log1pf(__expf(-fabsf(x)));
}

__device__ __forceinline__ float ciou_loss(float px,float py,float pw,float ph,
                                           float gx,float gy,float gw,float gh){
    const float eps = 1e-7f;
    float px1=px-pw*0.5f, py1=py-ph*0.5f, px2=px+pw*0.5f, py2=py+ph*0.5f;
    float gx1=gx-gw*0.5f, gy1=gy-gh*0.5f, gx2=gx+gw*0.5f, gy2=gy+gh*0.5f;
    float iw = fmaxf(fminf(px2,gx2)-fmaxf(px1,gx1), 0.f);
    float ih = fmaxf(fminf(py2,gy2)-fmaxf(py1,gy1), 0.f);
    float inter = iw*ih;
    float uni = pw*ph + gw*gh - inter + eps;
    float iou = inter/uni;
    float cw = fmaxf(px2,gx2)-fminf(px1,gx1);
    float ch = fmaxf(py2,gy2)-fminf(py1,gy1);
    float c2 = cw*cw + ch*ch + eps;
    float rho2 = (gx-px)*(gx-px) + (gy-py)*(gy-py);
    float d = atanf(gw/(gh+eps)) - atanf(pw/(ph+eps));
    float v = (4.0f/(PI_F*PI_F))*d*d;
    float alpha = v/(1.f-iou+v+eps);
    return 1.f - iou + rho2/c2 + alpha*v;
}

// ---------------- kernel 0: zero state ----------------
__global__ void initK(){
    int t = blockIdx.x*blockDim.x + threadIdx.x;
    if (t < NB*NA/4) ((int4*)g_amg)[t] = make_int4(0,0,0,0);
    if (t < NB*BMW) g_bitmap[t] = 0u;
    if (t < NB*4)   g_acc[t] = 0.f;
    if (t < NB)     g_nf[t] = 0;
}

// ---------------- kernel 1: direct in-center enumeration + dedup compaction ----------------
__global__ void markK(const float* __restrict__ tgt){
    int t = blockIdx.x*blockDim.x + threadIdx.x;
    const int total = NB*NM*3*36;
    if (t >= total) return;
    int cell = t % 36; int r = t / 36;
    int level = r % 3; int bm = r / 3;
    int b = bm / NM;
    const float* tr = tgt + bm*5;
    if (tr[0] < 0.f) return;
    float gx = tr[1]*INPUT_SZ, gy = tr[2]*INPUT_SZ;
    float s, cd; int f, base;
    if (level == 0){ s = 8.f;  cd = 12.f; f = 80; base = 0;    }
    else if (level == 1){ s = 16.f; cd = 24.f; f = 40; base = 6400; }
    else { s = 32.f; cd = 48.f; f = 20; base = 8000; }
    int kx = (int)floorf(gx/s), ky = (int)floorf(gy/s);
    int ix = kx - 2 + (cell % 6);
    int iy = ky - 2 + (cell / 6);
    if (ix < 0 || ix >= f || iy < 0 || iy >= f) return;
    float xc = (ix + 0.5f)*s, yc = (iy + 0.5f)*s;
    float c_l = xc - (gx - cd);
    float c_r = (gx + cd) - xc;
    float c_t = yc - (gy - cd);
    float c_b = (gy + cd) - yc;
    if (!(fminf(fminf(c_l,c_r), fminf(c_t,c_b)) > 0.f)) return;
    int a = base + iy*f + ix;
    unsigned bit = 1u << (a & 31);
    unsigned old = atomicOr(&g_bitmap[b*BMW + (a >> 5)], bit);
    if (!(old & bit)){
        int slot = atomicAdd(&g_nf[b], 1);
        if (slot < MAXF){
            g_flist[b*MAXF + slot] = a;
            g_cidx[b*NA + a] = slot;
        }
    }
}

// ---------------- kernel 2: warp-per-slot class-cost precompute ----------------
__global__ void gatherK(const float* __restrict__ pred){
    int b = blockIdx.y;
    int slot = blockIdx.x*8 + (threadIdx.x >> 5);
    int lane = threadIdx.x & 31;
    int nf = g_nf[b]; if (nf > MAXF) nf = MAXF;
    if (slot >= nf) return;
    int a = g_flist[b*MAXF + slot];
    const float* pr = pred + ((size_t)b*NA + a)*PRED_DIM;
    float sobj = sigmoid_f(pr[4]);
    float lp0, lp1, lp2=0.f, l1m0, l1m1, l1m2=0.f;
    {
        float p = sqrtf(sigmoid_f(pr[5+lane]) * sobj);
        lp0  = fmaxf(__logf(p),  -100.f);
        l1m0 = fmaxf(log1pf(-p), -100.f);
    }
    {
        float p = sqrtf(sigmoid_f(pr[5+lane+32]) * sobj);
        lp1  = fmaxf(__logf(p),  -100.f);
        l1m1 = fmaxf(log1pf(-p), -100.f);
    }
    if (lane < 16){
        float p = sqrtf(sigmoid_f(pr[5+lane+64]) * sobj);
        lp2  = fmaxf(__logf(p),  -100.f);
        l1m2 = fmaxf(log1pf(-p), -100.f);
    }
    float s1m = l1m0 + l1m1 + l1m2;
    #pragma unroll
    for (int s=16; s>=1; s>>=1) s1m += __shfl_xor_sync(0xffffffffu, s1m, s);
    float* dst = g_cls + ((size_t)(b*MAXF + slot))*NC;
    dst[lane]      = -lp0 - (s1m - l1m0);
    dst[lane+32]   = -lp1 - (s1m - l1m1);
    if (lane < 16) dst[lane+64] = -lp2 - (s1m - l1m2);
    if (lane == 0) g_boxc[b*MAXF + slot] = make_float4(pr[0], pr[1], pr[2], pr[3]);
}

// ---------------- kernel 3: block-per-row cost + top-k + scatter ----------------
__global__ void costK(const float* __restrict__ tgt){
    int m = blockIdx.x, b = blockIdx.y;
    int bm = b*NM + m;
    int t = threadIdx.x;                 // 128 threads, 4 warps
    int warp = t >> 5, lane = t & 31;
    const float* tr = tgt + bm*5;
    float c0 = tr[0];
    if (c0 < 0.f) return;                // padded GT (block-uniform)
    int gcls = (int)fminf(fmaxf(c0, 0.f), (float)(NC-1));
    float gx = tr[1]*INPUT_SZ, gy = tr[2]*INPUT_SZ, gw = tr[3]*INPUT_SZ, gh = tr[4]*INPUT_SZ;
    float areag = gw*gh;
    int nf = g_nf[b]; if (nf > MAXF) nf = MAXF;

    float cv[KTOP]; int ci[KTOP]; float iv[KTOP];
    #pragma unroll
    for (int k=0;k<KTOP;k++){ cv[k]=3.4e38f; ci[k]=0x7fffffff; iv[k]=0.f; }

    const int*    flst = g_flist + b*MAXF;
    const float4* boxp = g_boxc + b*MAXF;
    const float*  clsb = g_cls + (size_t)b*MAXF*NC + gcls;
    float* crow = g_costc + (size_t)bm * MAXF;

    for (int i = t; i < nf; i += 128){
        int a = flst[i];
        float xc, yc, cd; anchor_geom(a, xc, yc, cd);
        float c_l = xc - (gx - cd);
        float c_r = (gx + cd) - xc;
        float c_t = yc - (gy - cd);
        float c_b = (gy + cd) - yc;
        bool in_c = fminf(fminf(c_l,c_r), fminf(c_t,c_b)) > 0.f;

        float4 pb = boxp[i];
        float px=pb.x, py=pb.y, pw=pb.z, ph=pb.w;
        float tlx = fmaxf(gx-gw*0.5f, px-pw*0.5f);
        float tly = fmaxf(gy-gh*0.5f, py-ph*0.5f);
        float brx = fminf(gx+gw*0.5f, px+pw*0.5f);
        float bry = fminf(gy+gh*0.5f, py+ph*0.5f);
        float iou = 0.f;
        if (tlx<brx && tly<bry){
            float ai = (brx-tlx)*(bry-tly);
            iou = ai/(areag + pw*ph - ai);
        }
        float iou_cost = -__logf(iou + 1e-8f);
        float cls_cost = clsb[(size_t)i*NC];
        float cost = (cls_cost + 3.f*iou_cost) + (in_c ? 0.f : 1e6f);
        crow[i] = cost;

        if (cost < cv[KTOP-1] || (cost == cv[KTOP-1] && a < ci[KTOP-1])){
            cv[KTOP-1]=cost; ci[KTOP-1]=a;
            #pragma unroll
            for (int j=KTOP-1;j>0;j--){
                bool sw = cv[j] < cv[j-1] || (cv[j]==cv[j-1] && ci[j]<ci[j-1]);
                if (!sw) break;
                float tv=cv[j]; cv[j]=cv[j-1]; cv[j-1]=tv;
                int ti=ci[j]; ci[j]=ci[j-1]; ci[j-1]=ti;
            }
        }
        if (iou > iv[KTOP-1]){
            iv[KTOP-1]=iou;
            #pragma unroll
            for (int j=KTOP-1;j>0;j--){
                if (iv[j] <= iv[j-1]) break;
                float tv=iv[j]; iv[j]=iv[j-1]; iv[j-1]=tv;
            }
        }
    }

    // intra-warp snapshot butterfly (all static register indexing)
    #pragma unroll
    for (int d=16; d>=1; d>>=1){
        float pv[KTOP]; int pi[KTOP]; float pj[KTOP];
        #pragma unroll
        for (int k=0;k<KTOP;k++){
            pv[k] = __shfl_xor_sync(0xffffffffu, cv[k], d);
            pi[k] = __shfl_xor_sync(0xffffffffu, ci[k], d);
            pj[k] = __shfl_xor_sync(0xffffffffu, iv[k], d);
        }
        #pragma unroll
        for (int k=0;k<KTOP;k++){
            if (pv[k] < cv[KTOP-1] || (pv[k] == cv[KTOP-1] && pi[k] < ci[KTOP-1])){
                cv[KTOP-1]=pv[k]; ci[KTOP-1]=pi[k];
                #pragma unroll
                for (int j=KTOP-1;j>0;j--){
                    bool sw = cv[j] < cv[j-1] || (cv[j]==cv[j-1] && ci[j]<ci[j-1]);
                    if (!sw) break;
                    float tv=cv[j]; cv[j]=cv[j-1]; cv[j-1]=tv;
                    int ti=ci[j]; ci[j]=ci[j-1]; ci[j-1]=ti;
                }
            } else break;
        }
        #pragma unroll
        for (int k=0;k<KTOP;k++){
            if (pj[k] > iv[KTOP-1]){
                iv[KTOP-1]=pj[k];
                #pragma unroll
                for (int j=KTOP-1;j>0;j--){
                    if (iv[j] <= iv[j-1]) break;
                    float tv=iv[j]; iv[j]=iv[j-1]; iv[j-1]=tv;
                }
            } else break;
        }
    }

    // one smem hop: 4 warp-lists -> thread 0 serial 4-way merge
    __shared__ float swv[4][KTOP];
    __shared__ int   swi[4][KTOP];
    __shared__ float sjv[4][KTOP];
    if (lane == 0){
        #pragma unroll
        for (int k=0;k<KTOP;k++){ swv[warp][k]=cv[k]; swi[warp][k]=ci[k]; sjv[warp][k]=iv[k]; }
    }
    __syncthreads();
    if (t == 0){
        // dyn_k: 10 maxima across 4 descending lists
        int q0=0,q1=0,q2=0,q3=0;
        float sum = 0.f;
        #pragma unroll
        for (int k=0;k<KTOP;k++){
            float v0=sjv[0][q0], v1=sjv[1][q1], v2=sjv[2][q2], v3=sjv[3][q3];
            float va = v0 >= v1 ? v0 : v1; int la = v0 >= v1 ? 0 : 1;
            float vb = v2 >= v3 ? v2 : v3; int lb = v2 >= v3 ? 2 : 3;
            float vm = va >= vb ? va : vb; int lm = va >= vb ? la : lb;
            sum += vm;
            if (lm==0) q0++; else if (lm==1) q1++; else if (lm==2) q2++; else q3++;
        }
        int dk = (int)sum;
        dk = dk < 1 ? 1 : (dk > KTOP ? KTOP : dk);
        // top-dk costs: merge 4 ascending (cost,idx) lists
        int p0=0,p1=0,p2=0,p3=0;
        for (int k=0;k<dk;k++){
            float v0=swv[0][p0], v1=swv[1][p1], v2=swv[2][p2], v3=swv[3][p3];
            int   i0=swi[0][p0], i1=swi[1][p1], i2=swi[2][p2], i3=swi[3][p3];
            bool a01 = v0 < v1 || (v0==v1 && i0<i1);
            float va = a01?v0:v1; int ia = a01?i0:i1; int la = a01?0:1;
            bool a23 = v2 < v3 || (v2==v3 && i2<i3);
            float vb = a23?v2:v3; int ib = a23?i2:i3; int lb = a23?2:3;
            bool ab = va < vb || (va==vb && ia<ib);
            int im = ab?ia:ib; int lm = ab?la:lb;
            if (lm==0) p0++; else if (lm==1) p1++; else if (lm==2) p2++; else p3++;
            if (im >= 0 && im < NA)
                atomicAdd(&g_amg[b*NA + im], 0x10000 + m);
        }
    }
}

// ---------------- kernel 4: losses (+ inline duplicate resolution) ----------------
__global__ void lossK(const float* __restrict__ pred, const float* __restrict__ tgt){
    int b = blockIdx.y;
    int a = blockIdx.x*blockDim.x + threadIdx.x;
    int t = threadIdx.x;
    __shared__ float stg[NM*5];
    for (int i=t; i<NM*5; i+=blockDim.x) stg[i]=tgt[b*NM*5+i];
    __syncthreads();
    float o=0.f, cl=0.f, bx=0.f, np=0.f;
    if (a < NA){
        const float* pr = pred + ((size_t)b*NA + a)*PRED_DIM;
        int v = g_amg[b*NA + a];
        int cnt = v >> 16;
        int mg = -1;
        if (cnt == 1) mg = v & 0xffff;
        else if (cnt > 1){
            int slot = g_cidx[b*NA + a];
            float best = 3.4e38f; int bi = 0;
            for (int m=0;m<NM;m++){
                if (stg[m*5] < 0.f) continue;
                float c = g_costc[((size_t)(b*NM+m))*MAXF + slot];
                if (c < best){ best=c; bi=m; }
            }
            mg = bi;
        }
        float tf = (mg >= 0) ? 1.f : 0.f;
        o = bce_logits(pr[4], tf);
        if (mg >= 0){
            np = 1.f;
            int gc = (int)fminf(fmaxf(stg[mg*5], 0.f), (float)(NC-1));
            #pragma unroll 4
            for (int c=0;c<NC;c++)
                cl += bce_logits(pr[5+c], (c==gc)?1.f:0.f);
            float gx=stg[mg*5+1]*INPUT_SZ, gy=stg[mg*5+2]*INPUT_SZ;
            float gw=stg[mg*5+3]*INPUT_SZ, gh=stg[mg*5+4]*INPUT_SZ;
            bx = ciou_loss(pr[0],pr[1],pr[2],pr[3], gx,gy,gw,gh);
        }
    }
    __shared__ float r0[256], r1[256], r2[256], r3[256];
    r0[t]=o; r1[t]=cl; r2[t]=bx; r3[t]=np;
    __syncthreads();
    for (int s=128; s>=1; s>>=1){
        if (t < s){ r0[t]+=r0[t+s]; r1[t]+=r1[t+s]; r2[t]+=r2[t+s]; r3[t]+=r3[t+s]; }
        __syncthreads();
    }
    if (t==0){
        atomicAdd(&g_acc[b*4+0], r0[0]);
        atomicAdd(&g_acc[b*4+1], r1[0]);
        atomicAdd(&g_acc[b*4+2], r2[0]);
        atomicAdd(&g_acc[b*4+3], r3[0]);
    }
}

// ---------------- kernel 5: final reduction ----------------
__global__ void finalK(float* __restrict__ out){
    int t = threadIdx.x;
    float obj=0.f, cls=0.f, box=0.f, np=0.f;
    if (t < NB){
        np  = g_acc[t*4+3];
        obj = g_acc[t*4+0] / (float)NA;
        cls = (np > 0.f) ? g_acc[t*4+1]/(np*(float)NC) : 0.f;
        box = (np > 0.f) ? g_acc[t*4+2]/np : 0.f;
    }
    for (int s=16; s>=1; s>>=1){
        obj += __shfl_down_sync(0xffffffffu, obj, s);
        cls += __shfl_down_sync(0xffffffffu, cls, s);
        box += __shfl_down_sync(0xffffffffu, box, s);
        np  += __shfl_down_sync(0xffffffffu, np,  s);
    }
    if (t==0){
        float total = (5.f*box + obj + cls) / fmaxf(np, 1.f);
        out[0]=total; out[1]=box; out[2]=obj; out[3]=cls; out[4]=np;
    }
}

// ---------------- launch ----------------
extern "C" void kernel_launch(void* const* d_in, const int* in_sizes, int n_in,
                              void* d_out, int out_size){
    const float* pred = (const float*)d_in[0];   // [B, A, 85]
    const float* tgt  = (const float*)d_in[1];   // [B, M, 5]
    float* out = (float*)d_out;                  // 5 floats

    initK<<<(NB*NA/4 + 255)/256, 256>>>();
    markK<<<(NB*NM*3*36 + 255)/256, 256>>>(tgt);
    gatherK<<<dim3(MAXF/8, NB), 256>>>(pred);
    costK<<<dim3(NM, NB), 128>>>(tgt);
    dim3 gA((NA+255)/256, NB);
    lossK<<<gA, 256>>>(pred, tgt);
    finalK<<<1, 32>>>(out);
}

// round 8
// speedup vs baseline: 1.7185x; 1.7185x over previous
#include <cuda_runtime.h>
#include <math.h>

#define NB 32
#define NA 8400
#define NM 50
#define NC 80
#define KTOP 10
#define PRED_DIM 85
#define MAXF 2048
#define BMW 263
#define INPUT_SZ 640.0f
#define PI_F 3.14159265358979323846f

// ---------------- scratch ----------------
__device__ int      g_nf[NB];
__device__ int      g_flist[NB*MAXF];
__device__ int      g_cidx[NB*NA];
__device__ unsigned g_bitmap[NB*BMW];
__device__ float    g_cls[NB*MAXF*NC];        // cls_cost term, [b][slot][c]
__device__ float4   g_boxc[NB*MAXF];
__device__ float    g_costc[NB*NM*MAXF];      // dup resolution only
__device__ int      g_amg[NB*NA];             // (count<<16) | sum_of_m
__device__ float    g_acc[NB*4];

// ---------------- helpers ----------------
__device__ __forceinline__ void anchor_geom(int a, float& xc, float& yc, float& cd){
    if (a < 6400){
        int y = a / 80, x = a - y*80;
        xc = (x + 0.5f)*8.f;  yc = (y + 0.5f)*8.f;  cd = 12.f;
    } else if (a < 8000){
        int i = a - 6400; int y = i / 40, x = i - y*40;
        xc = (x + 0.5f)*16.f; yc = (y + 0.5f)*16.f; cd = 24.f;
    } else {
        int i = a - 8000; int y = i / 20, x = i - y*20;
        xc = (x + 0.5f)*32.f; yc = (y + 0.5f)*32.f; cd = 48.f;
    }
}

__device__ __forceinline__ float sigmoid_f(float x){
    return 1.f / (1.f + __expf(-x));
}

__device__ __forceinline__ unsigned sortable_f(float f){
    unsigned u = __float_as_uint(f);
    return (u & 0x80000000u) ? ~u : (u | 0x80000000u);
}

__device__ __forceinline__ float bce_logits(float x, float t){
    return fmaxf(x, 0.f) - x*t + log1pf(__expf(-fabsf(x)));
}

__device__ __forceinline__ float ciou_loss(float px,float py,float pw,float ph,
                                           float gx,float gy,float gw,float gh){
    const float eps = 1e-7f;
    float px1=px-pw*0.5f, py1=py-ph*0.5f, px2=px+pw*0.5f, py2=py+ph*0.5f;
    float gx1=gx-gw*0.5f, gy1=gy-gh*0.5f, gx2=gx+gw*0.5f, gy2=gy+gh*0.5f;
    float iw = fmaxf(fminf(px2,gx2)-fmaxf(px1,gx1), 0.f);
    float ih = fmaxf(fminf(py2,gy2)-fmaxf(py1,gy1), 0.f);
    float inter = iw*ih;
    float uni = pw*ph + gw*gh - inter + eps;
    float iou = inter/uni;
    float cw = fmaxf(px2,gx2)-fminf(px1,gx1);
    float ch = fmaxf(py2,gy2)-fminf(py1,gy1);
    float c2 = cw*cw + ch*ch + eps;
    float rho2 = (gx-px)*(gx-px) + (gy-py)*(gy-py);
    float d = atanf(gw/(gh+eps)) - atanf(pw/(ph+eps));
    float v = (4.0f/(PI_F*PI_F))*d*d;
    float alpha = v/(1.f-iou+v+eps);
    return 1.f - iou + rho2/c2 + alpha*v;
}

// ---------------- kernel 0: zero state ----------------
__global__ void initK(){
    int t = blockIdx.x*blockDim.x + threadIdx.x;
    if (t < NB*NA/4) ((int4*)g_amg)[t] = make_int4(0,0,0,0);
    if (t < NB*BMW) g_bitmap[t] = 0u;
    if (t < NB*4)   g_acc[t] = 0.f;
    if (t < NB)     g_nf[t] = 0;
}

// ---------------- kernel 1: direct in-center enumeration + dedup compaction ----------------
__global__ void markK(const float* __restrict__ tgt){
    int t = blockIdx.x*blockDim.x + threadIdx.x;
    const int total = NB*NM*3*36;
    if (t >= total) return;
    int cell = t % 36; int r = t / 36;
    int level = r % 3; int bm = r / 3;
    int b = bm / NM;
    const float* tr = tgt + bm*5;
    if (tr[0] < 0.f) return;
    float gx = tr[1]*INPUT_SZ, gy = tr[2]*INPUT_SZ;
    float s, cd; int f, base;
    if (level == 0){ s = 8.f;  cd = 12.f; f = 80; base = 0;    }
    else if (level == 1){ s = 16.f; cd = 24.f; f = 40; base = 6400; }
    else { s = 32.f; cd = 48.f; f = 20; base = 8000; }
    int kx = (int)floorf(gx/s), ky = (int)floorf(gy/s);
    int ix = kx - 2 + (cell % 6);
    int iy = ky - 2 + (cell / 6);
    if (ix < 0 || ix >= f || iy < 0 || iy >= f) return;
    float xc = (ix + 0.5f)*s, yc = (iy + 0.5f)*s;
    float c_l = xc - (gx - cd);
    float c_r = (gx + cd) - xc;
    float c_t = yc - (gy - cd);
    float c_b = (gy + cd) - yc;
    if (!(fminf(fminf(c_l,c_r), fminf(c_t,c_b)) > 0.f)) return;
    int a = base + iy*f + ix;
    unsigned bit = 1u << (a & 31);
    unsigned old = atomicOr(&g_bitmap[b*BMW + (a >> 5)], bit);
    if (!(old & bit)){
        int slot = atomicAdd(&g_nf[b], 1);
        if (slot < MAXF){
            g_flist[b*MAXF + slot] = a;
            g_cidx[b*NA + a] = slot;
        }
    }
}

// ---------------- kernel 2: warp-per-slot class-cost precompute ----------------
__global__ void gatherK(const float* __restrict__ pred){
    int b = blockIdx.y;
    int slot = blockIdx.x*8 + (threadIdx.x >> 5);
    int lane = threadIdx.x & 31;
    int nf = g_nf[b]; if (nf > MAXF) nf = MAXF;
    if (slot >= nf) return;
    int a = g_flist[b*MAXF + slot];
    const float* pr = pred + ((size_t)b*NA + a)*PRED_DIM;
    float sobj = sigmoid_f(pr[4]);
    float lp0, lp1, lp2=0.f, l1m0, l1m1, l1m2=0.f;
    {
        float p = sqrtf(sigmoid_f(pr[5+lane]) * sobj);
        lp0  = fmaxf(__logf(p),  -100.f);
        l1m0 = fmaxf(log1pf(-p), -100.f);
    }
    {
        float p = sqrtf(sigmoid_f(pr[5+lane+32]) * sobj);
        lp1  = fmaxf(__logf(p),  -100.f);
        l1m1 = fmaxf(log1pf(-p), -100.f);
    }
    if (lane < 16){
        float p = sqrtf(sigmoid_f(pr[5+lane+64]) * sobj);
        lp2  = fmaxf(__logf(p),  -100.f);
        l1m2 = fmaxf(log1pf(-p), -100.f);
    }
    float s1m = l1m0 + l1m1 + l1m2;
    #pragma unroll
    for (int s=16; s>=1; s>>=1) s1m += __shfl_xor_sync(0xffffffffu, s1m, s);
    float* dst = g_cls + ((size_t)(b*MAXF + slot))*NC;
    dst[lane]      = -lp0 - (s1m - l1m0);
    dst[lane+32]   = -lp1 - (s1m - l1m1);
    if (lane < 16) dst[lane+64] = -lp2 - (s1m - l1m2);
    if (lane == 0) g_boxc[b*MAXF + slot] = make_float4(pr[0], pr[1], pr[2], pr[3]);
}

// ---------------- kernel 3: block-per-row cost + smem merge-tree top-k + scatter ----------------
__global__ void costK(const float* __restrict__ tgt){
    int m = blockIdx.x, b = blockIdx.y;
    int bm = b*NM + m;
    int t = threadIdx.x;                 // 128 threads
    const float* tr = tgt + bm*5;
    float c0 = tr[0];
    if (c0 < 0.f) return;                // padded GT (block-uniform)
    int gcls = (int)fminf(fmaxf(c0, 0.f), (float)(NC-1));
    float gx = tr[1]*INPUT_SZ, gy = tr[2]*INPUT_SZ, gw = tr[3]*INPUT_SZ, gh = tr[4]*INPUT_SZ;
    float areag = gw*gh;
    int nf = g_nf[b]; if (nf > MAXF) nf = MAXF;

    unsigned long long kq[KTOP];         // ascending (cost,anchor) keys
    float iq[KTOP];                      // descending ious
    #pragma unroll
    for (int k=0;k<KTOP;k++){ kq[k]=0xFFFFFFFFFFFFFFFFull; iq[k]=0.f; }

    const int*    flst = g_flist + b*MAXF;
    const float4* boxp = g_boxc + b*MAXF;
    const float*  clsb = g_cls + (size_t)b*MAXF*NC + gcls;
    float* crow = g_costc + (size_t)bm * MAXF;

    for (int i = t; i < nf; i += 128){
        int a = flst[i];
        float xc, yc, cd; anchor_geom(a, xc, yc, cd);
        float c_l = xc - (gx - cd);
        float c_r = (gx + cd) - xc;
        float c_t = yc - (gy - cd);
        float c_b = (gy + cd) - yc;
        bool in_c = fminf(fminf(c_l,c_r), fminf(c_t,c_b)) > 0.f;

        float4 pb = boxp[i];
        float px=pb.x, py=pb.y, pw=pb.z, ph=pb.w;
        float tlx = fmaxf(gx-gw*0.5f, px-pw*0.5f);
        float tly = fmaxf(gy-gh*0.5f, py-ph*0.5f);
        float brx = fminf(gx+gw*0.5f, px+pw*0.5f);
        float bry = fminf(gy+gh*0.5f, py+ph*0.5f);
        float iou = 0.f;
        if (tlx<brx && tly<bry){
            float ai = (brx-tlx)*(bry-tly);
            iou = ai/(areag + pw*ph - ai);
        }
        float cost = (clsb[(size_t)i*NC] - 3.f*__logf(iou + 1e-8f)) + (in_c ? 0.f : 1e6f);
        crow[i] = cost;

        unsigned long long key = ((unsigned long long)sortable_f(cost) << 32) | (unsigned)a;
        if (key < kq[KTOP-1]){
            kq[KTOP-1]=key;
            #pragma unroll
            for (int j=KTOP-1;j>0;j--){
                if (kq[j] >= kq[j-1]) break;
                unsigned long long tv=kq[j]; kq[j]=kq[j-1]; kq[j-1]=tv;
            }
        }
        if (iou > iq[KTOP-1]){
            iq[KTOP-1]=iou;
            #pragma unroll
            for (int j=KTOP-1;j>0;j--){
                if (iq[j] <= iq[j-1]) break;
                float tv=iq[j]; iq[j]=iq[j-1]; iq[j-1]=tv;
            }
        }
    }

    // smem ping-pong merge tree: 128 sorted lists -> 1, two-pointer, O(K) per merge
    __shared__ unsigned long long sk[2][128][KTOP];
    __shared__ float              si[2][128][KTOP];
    #pragma unroll
    for (int k=0;k<KTOP;k++){ sk[0][t][k]=kq[k]; si[0][t][k]=iq[k]; }

    int p = 0;
    for (int s=64; s>=1; s>>=1){
        __syncthreads();
        if (t < s){
            const unsigned long long* A = sk[p][t];
            const unsigned long long* Bk = sk[p][t+s];
            unsigned long long* D = sk[p^1][t];
            int i=0, j=0;
            unsigned long long av = A[0], bv = Bk[0];
            #pragma unroll
            for (int k=0;k<KTOP;k++){
                if (av <= bv){ D[k]=av; i++; av = (i<KTOP)? A[i] : 0xFFFFFFFFFFFFFFFFull; }
                else         { D[k]=bv; j++; bv = (j<KTOP)? Bk[j]: 0xFFFFFFFFFFFFFFFFull; }
            }
            const float* Ai = si[p][t];
            const float* Bi = si[p][t+s];
            float* Di = si[p^1][t];
            i=0; j=0;
            float af = Ai[0], bf = Bi[0];
            #pragma unroll
            for (int k=0;k<KTOP;k++){
                if (af >= bf){ Di[k]=af; i++; af = (i<KTOP)? Ai[i] : -1.f; }
                else         { Di[k]=bf; j++; bf = (j<KTOP)? Bi[j] : -1.f; }
            }
        }
        p ^= 1;
    }
    __syncthreads();

    if (t == 0){
        float sum = 0.f;
        #pragma unroll
        for (int k=0;k<KTOP;k++) sum += si[p][0][k];
        int dk = (int)sum;                       // trunc == astype(int32)
        dk = dk < 1 ? 1 : (dk > KTOP ? KTOP : dk);
        for (int k=0;k<dk;k++){
            int a = (int)(sk[p][0][k] & 0xFFFFFFFFull);
            if (a >= 0 && a < NA)
                atomicAdd(&g_amg[b*NA + a], 0x10000 + m);
        }
    }
}

// ---------------- kernel 4: losses (+ inline duplicate resolution) ----------------
__global__ void lossK(const float* __restrict__ pred, const float* __restrict__ tgt){
    int b = blockIdx.y;
    int a = blockIdx.x*blockDim.x + threadIdx.x;
    int t = threadIdx.x;
    __shared__ float stg[NM*5];
    for (int i=t; i<NM*5; i+=blockDim.x) stg[i]=tgt[b*NM*5+i];
    __syncthreads();
    float o=0.f, cl=0.f, bx=0.f, np=0.f;
    if (a < NA){
        const float* pr = pred + ((size_t)b*NA + a)*PRED_DIM;
        int v = g_amg[b*NA + a];
        int cnt = v >> 16;
        int mg = -1;
        if (cnt == 1) mg = v & 0xffff;
        else if (cnt > 1){
            int slot = g_cidx[b*NA + a];
            float best = 3.4e38f; int bi = 0;
            for (int m=0;m<NM;m++){
                if (stg[m*5] < 0.f) continue;
                float c = g_costc[((size_t)(b*NM+m))*MAXF + slot];
                if (c < best){ best=c; bi=m; }
            }
            mg = bi;
        }
        float tf = (mg >= 0) ? 1.f : 0.f;
        o = bce_logits(pr[4], tf);
        if (mg >= 0){
            np = 1.f;
            int gc = (int)fminf(fmaxf(stg[mg*5], 0.f), (float)(NC-1));
            #pragma unroll 4
            for (int c=0;c<NC;c++)
                cl += bce_logits(pr[5+c], (c==gc)?1.f:0.f);
            float gx=stg[mg*5+1]*INPUT_SZ, gy=stg[mg*5+2]*INPUT_SZ;
            float gw=stg[mg*5+3]*INPUT_SZ, gh=stg[mg*5+4]*INPUT_SZ;
            bx = ciou_loss(pr[0],pr[1],pr[2],pr[3], gx,gy,gw,gh);
        }
    }
    __shared__ float r0[256], r1[256], r2[256], r3[256];
    r0[t]=o; r1[t]=cl; r2[t]=bx; r3[t]=np;
    __syncthreads();
    for (int s=128; s>=1; s>>=1){
        if (t < s){ r0[t]+=r0[t+s]; r1[t]+=r1[t+s]; r2[t]+=r2[t+s]; r3[t]+=r3[t+s]; }
        __syncthreads();
    }
    if (t==0){
        atomicAdd(&g_acc[b*4+0], r0[0]);
        atomicAdd(&g_acc[b*4+1], r1[0]);
        atomicAdd(&g_acc[b*4+2], r2[0]);
        atomicAdd(&g_acc[b*4+3], r3[0]);
    }
}

// ---------------- kernel 5: final reduction ----------------
__global__ void finalK(float* __restrict__ out){
    int t = threadIdx.x;
    float obj=0.f, cls=0.f, box=0.f, np=0.f;
    if (t < NB){
        np  = g_acc[t*4+3];
        obj = g_acc[t*4+0] / (float)NA;
        cls = (np > 0.f) ? g_acc[t*4+1]/(np*(float)NC) : 0.f;
        box = (np > 0.f) ? g_acc[t*4+2]/np : 0.f;
    }
    for (int s=16; s>=1; s>>=1){
        obj += __shfl_down_sync(0xffffffffu, obj, s);
        cls += __shfl_down_sync(0xffffffffu, cls, s);
        box += __shfl_down_sync(0xffffffffu, box, s);
        np  += __shfl_down_sync(0xffffffffu, np,  s);
    }
    if (t==0){
        float total = (5.f*box + obj + cls) / fmaxf(np, 1.f);
        out[0]=total; out[1]=box; out[2]=obj; out[3]=cls; out[4]=np;
    }
}

// ---------------- launch ----------------
extern "C" void kernel_launch(void* const* d_in, const int* in_sizes, int n_in,
                              void* d_out, int out_size){
    const float* pred = (const float*)d_in[0];   // [B, A, 85]
    const float* tgt  = (const float*)d_in[1];   // [B, M, 5]
    float* out = (float*)d_out;                  // 5 floats

    initK<<<(NB*NA/4 + 255)/256, 256>>>();
    markK<<<(NB*NM*3*36 + 255)/256, 256>>>(tgt);
    gatherK<<<dim3(MAXF/8, NB), 256>>>(pred);
    costK<<<dim3(NM, NB), 128>>>(tgt);
    dim3 gA((NA+255)/256, NB);
    lossK<<<gA, 256>>>(pred, tgt);
    finalK<<<1, 32>>>(out);
}

// round 9
// speedup vs baseline: 2.1903x; 1.2745x over previous
#include <cuda_runtime.h>
#include <math.h>

#define NB 32
#define NA 8400
#define NM 50
#define NC 80
#define KTOP 10
#define PRED_DIM 85
#define MAXF 1536
#define BMW 263
#define INPUT_SZ 640.0f
#define PI_F 3.14159265358979323846f

// ---------------- scratch ----------------
__device__ int      g_nf[NB];
__device__ int      g_flist[NB*MAXF];
__device__ unsigned g_bitmap[NB*BMW];
__device__ float    g_cls[NB*MAXF*NC];        // cls_cost term, [b][slot][c]
__device__ float4   g_boxc[NB*MAXF];
__device__ float    g_costc[NB*NM*MAXF];      // dup resolution only
__device__ int      g_amg[NB*NA];             // (count<<16) | sum_of_m
__device__ float    g_acc[NB*4];

// ---------------- helpers ----------------
__device__ __forceinline__ void anchor_geom(int a, float& xc, float& yc, float& cd){
    if (a < 6400){
        int y = a / 80, x = a - y*80;
        xc = (x + 0.5f)*8.f;  yc = (y + 0.5f)*8.f;  cd = 12.f;
    } else if (a < 8000){
        int i = a - 6400; int y = i / 40, x = i - y*40;
        xc = (x + 0.5f)*16.f; yc = (y + 0.5f)*16.f; cd = 24.f;
    } else {
        int i = a - 8000; int y = i / 20, x = i - y*20;
        xc = (x + 0.5f)*32.f; yc = (y + 0.5f)*32.f; cd = 48.f;
    }
}

__device__ __forceinline__ float sigmoid_f(float x){
    return 1.f / (1.f + __expf(-x));
}

__device__ __forceinline__ unsigned sortable_f(float f){
    unsigned u = __float_as_uint(f);
    return (u & 0x80000000u) ? ~u : (u | 0x80000000u);
}

__device__ __forceinline__ float bce_logits(float x, float t){
    return fmaxf(x, 0.f) - x*t + log1pf(__expf(-fabsf(x)));
}

__device__ __forceinline__ float ciou_loss(float px,float py,float pw,float ph,
                                           float gx,float gy,float gw,float gh){
    const float eps = 1e-7f;
    float px1=px-pw*0.5f, py1=py-ph*0.5f, px2=px+pw*0.5f, py2=py+ph*0.5f;
    float gx1=gx-gw*0.5f, gy1=gy-gh*0.5f, gx2=gx+gw*0.5f, gy2=gy+gh*0.5f;
    float iw = fmaxf(fminf(px2,gx2)-fmaxf(px1,gx1), 0.f);
    float ih = fmaxf(fminf(py2,gy2)-fmaxf(py1,gy1), 0.f);
    float inter = iw*ih;
    float uni = pw*ph + gw*gh - inter + eps;
    float iou = inter/uni;
    float cw = fmaxf(px2,gx2)-fminf(px1,gx1);
    float ch = fmaxf(py2,gy2)-fminf(py1,gy1);
    float c2 = cw*cw + ch*ch + eps;
    float rho2 = (gx-px)*(gx-px) + (gy-py)*(gy-py);
    float d = atanf(gw/(gh+eps)) - atanf(pw/(ph+eps));
    float v = (4.0f/(PI_F*PI_F))*d*d;
    float alpha = v/(1.f-iou+v+eps);
    return 1.f - iou + rho2/c2 + alpha*v;
}

// ---------------- kernel 0: zero state ----------------
__global__ void initK(){
    int t = blockIdx.x*blockDim.x + threadIdx.x;
    if (t < NB*NA/4) ((int4*)g_amg)[t] = make_int4(0,0,0,0);
    if (t < NB*BMW) g_bitmap[t] = 0u;
    if (t < NB*4)   g_acc[t] = 0.f;
    if (t < NB)     g_nf[t] = 0;
}

// ---------------- kernel 1: direct in-center enumeration + dedup compaction ----------------
__global__ void markK(const float* __restrict__ tgt){
    int t = blockIdx.x*blockDim.x + threadIdx.x;
    const int total = NB*NM*3*36;
    if (t >= total) return;
    int cell = t % 36; int r = t / 36;
    int level = r % 3; int bm = r / 3;
    int b = bm / NM;
    const float* tr = tgt + bm*5;
    if (tr[0] < 0.f) return;
    float gx = tr[1]*INPUT_SZ, gy = tr[2]*INPUT_SZ;
    float s, cd; int f, base;
    if (level == 0){ s = 8.f;  cd = 12.f; f = 80; base = 0;    }
    else if (level == 1){ s = 16.f; cd = 24.f; f = 40; base = 6400; }
    else { s = 32.f; cd = 48.f; f = 20; base = 8000; }
    int kx = (int)floorf(gx/s), ky = (int)floorf(gy/s);
    int ix = kx - 2 + (cell % 6);
    int iy = ky - 2 + (cell / 6);
    if (ix < 0 || ix >= f || iy < 0 || iy >= f) return;
    float xc = (ix + 0.5f)*s, yc = (iy + 0.5f)*s;
    float c_l = xc - (gx - cd);
    float c_r = (gx + cd) - xc;
    float c_t = yc - (gy - cd);
    float c_b = (gy + cd) - yc;
    if (!(fminf(fminf(c_l,c_r), fminf(c_t,c_b)) > 0.f)) return;
    int a = base + iy*f + ix;
    unsigned bit = 1u << (a & 31);
    unsigned old = atomicOr(&g_bitmap[b*BMW + (a >> 5)], bit);
    if (!(old & bit)){
        int slot = atomicAdd(&g_nf[b], 1);
        if (slot < MAXF) g_flist[b*MAXF + slot] = a;
    }
}

// ---------------- kernel 2: warp-per-slot class-cost precompute ----------------
__global__ void gatherK(const float* __restrict__ pred){
    int b = blockIdx.y;
    int slot = blockIdx.x*8 + (threadIdx.x >> 5);
    int lane = threadIdx.x & 31;
    int nf = g_nf[b]; if (nf > MAXF) nf = MAXF;
    if (slot >= nf) return;
    int a = g_flist[b*MAXF + slot];
    const float* pr = pred + ((size_t)b*NA + a)*PRED_DIM;
    float sobj = sigmoid_f(pr[4]);
    float lp0, lp1, lp2=0.f, l1m0, l1m1, l1m2=0.f;
    {
        float p = sqrtf(sigmoid_f(pr[5+lane]) * sobj);
        lp0  = fmaxf(__logf(p),  -100.f);
        l1m0 = fmaxf(log1pf(-p), -100.f);
    }
    {
        float p = sqrtf(sigmoid_f(pr[5+lane+32]) * sobj);
        lp1  = fmaxf(__logf(p),  -100.f);
        l1m1 = fmaxf(log1pf(-p), -100.f);
    }
    if (lane < 16){
        float p = sqrtf(sigmoid_f(pr[5+lane+64]) * sobj);
        lp2  = fmaxf(__logf(p),  -100.f);
        l1m2 = fmaxf(log1pf(-p), -100.f);
    }
    float s1m = l1m0 + l1m1 + l1m2;
    #pragma unroll
    for (int s=16; s>=1; s>>=1) s1m += __shfl_xor_sync(0xffffffffu, s1m, s);
    float* dst = g_cls + ((size_t)(b*MAXF + slot))*NC;
    dst[lane]      = -lp0 - (s1m - l1m0);
    dst[lane+32]   = -lp1 - (s1m - l1m1);
    if (lane < 16) dst[lane+64] = -lp2 - (s1m - l1m2);
    if (lane == 0) g_boxc[b*MAXF + slot] = make_float4(pr[0], pr[1], pr[2], pr[3]);
}

// ---------------- kernel 3: block-per-row cost + shrinking merge tree + scatter ----------------
__global__ void __launch_bounds__(128, 7) costK(const float* __restrict__ tgt){
    int m = blockIdx.x, b = blockIdx.y;
    int bm = b*NM + m;
    int t = threadIdx.x;                 // 128 threads
    const float* tr = tgt + bm*5;
    float c0 = tr[0];
    if (c0 < 0.f) return;                // padded GT (block-uniform)
    int gcls = (int)fminf(fmaxf(c0, 0.f), (float)(NC-1));
    float gx = tr[1]*INPUT_SZ, gy = tr[2]*INPUT_SZ, gw = tr[3]*INPUT_SZ, gh = tr[4]*INPUT_SZ;
    float areag = gw*gh;
    int nf = g_nf[b]; if (nf > MAXF) nf = MAXF;

    unsigned long long kq[KTOP];         // ascending (cost,anchor) keys
    float iq[KTOP];                      // descending ious
    #pragma unroll
    for (int k=0;k<KTOP;k++){ kq[k]=0xFFFFFFFFFFFFFFFFull; iq[k]=0.f; }

    const int*    flst = g_flist + b*MAXF;
    const float4* boxp = g_boxc + b*MAXF;
    const float*  clsb = g_cls + (size_t)b*MAXF*NC + gcls;
    float* crow = g_costc + (size_t)bm * MAXF;

    for (int i = t; i < nf; i += 128){
        int a = flst[i];
        float xc, yc, cd; anchor_geom(a, xc, yc, cd);
        float c_l = xc - (gx - cd);
        float c_r = (gx + cd) - xc;
        float c_t = yc - (gy - cd);
        float c_b = (gy + cd) - yc;
        bool in_c = fminf(fminf(c_l,c_r), fminf(c_t,c_b)) > 0.f;

        float4 pb = boxp[i];
        float px=pb.x, py=pb.y, pw=pb.z, ph=pb.w;
        float tlx = fmaxf(gx-gw*0.5f, px-pw*0.5f);
        float tly = fmaxf(gy-gh*0.5f, py-ph*0.5f);
        float brx = fminf(gx+gw*0.5f, px+pw*0.5f);
        float bry = fminf(gy+gh*0.5f, py+ph*0.5f);
        float iou = 0.f;
        if (tlx<brx && tly<bry){
            float ai = (brx-tlx)*(bry-tly);
            iou = ai/(areag + pw*ph - ai);
        }
        float cost = (clsb[(size_t)i*NC] - 3.f*__logf(iou + 1e-8f)) + (in_c ? 0.f : 1e6f);
        crow[i] = cost;

        unsigned long long key = ((unsigned long long)sortable_f(cost) << 32) | (unsigned)a;
        if (key < kq[KTOP-1]){
            kq[KTOP-1]=key;
            #pragma unroll
            for (int j=KTOP-1;j>0;j--){
                if (kq[j] >= kq[j-1]) break;
                unsigned long long tv=kq[j]; kq[j]=kq[j-1]; kq[j-1]=tv;
            }
        }
        if (iou > iq[KTOP-1]){
            iq[KTOP-1]=iou;
            #pragma unroll
            for (int j=KTOP-1;j>0;j--){
                if (iq[j] <= iq[j-1]) break;
                float tv=iq[j]; iq[j]=iq[j-1]; iq[j-1]=tv;
            }
        }
    }

    // shrinking alternate-buffer merge tree: A(128 lists) <-> B(64 lists)
    __shared__ unsigned long long skA[128*KTOP];
    __shared__ unsigned long long skB[64*KTOP];
    __shared__ float              siA[128*KTOP];
    __shared__ float              siB[64*KTOP];
    #pragma unroll
    for (int k=0;k<KTOP;k++){ skA[t*KTOP+k]=kq[k]; siA[t*KTOP+k]=iq[k]; }

    unsigned long long* krd = skA; unsigned long long* kwr = skB;
    float* ird = siA; float* iwr = siB;
    for (int s=64; s>=1; s>>=1){
        __syncthreads();
        if (t < s){
            const unsigned long long* A = krd + t*KTOP;
            const unsigned long long* Bk = krd + (t+s)*KTOP;
            unsigned long long* D = kwr + t*KTOP;
            int i=0, j=0;
            unsigned long long av = A[0], bv = Bk[0];
            #pragma unroll
            for (int k=0;k<KTOP;k++){
                if (av <= bv){ D[k]=av; i++; av = (i<KTOP)? A[i] : 0xFFFFFFFFFFFFFFFFull; }
                else         { D[k]=bv; j++; bv = (j<KTOP)? Bk[j]: 0xFFFFFFFFFFFFFFFFull; }
            }
            const float* Ai = ird + t*KTOP;
            const float* Bi = ird + (t+s)*KTOP;
            float* Di = iwr + t*KTOP;
            i=0; j=0;
            float af = Ai[0], bf = Bi[0];
            #pragma unroll
            for (int k=0;k<KTOP;k++){
                if (af >= bf){ Di[k]=af; i++; af = (i<KTOP)? Ai[i] : -1.f; }
                else         { Di[k]=bf; j++; bf = (j<KTOP)? Bi[j] : -1.f; }
            }
        }
        { unsigned long long* tk=krd; krd=kwr; kwr=tk; }
        { float* ti=ird; ird=iwr; iwr=ti; }
    }
    __syncthreads();

    if (t == 0){
        float sum = 0.f;
        #pragma unroll
        for (int k=0;k<KTOP;k++) sum += ird[k];
        int dk = (int)sum;                       // trunc == astype(int32)
        dk = dk < 1 ? 1 : (dk > KTOP ? KTOP : dk);
        for (int k=0;k<dk;k++){
            int a = (int)(krd[k] & 0xFFFFFFFFull);
            if (a >= 0 && a < NA)
                atomicAdd(&g_amg[b*NA + a], 0x10000 + m);
        }
    }
}

// ---------------- kernel 4: obj loss over all anchors ----------------
__global__ void lossK(const float* __restrict__ pred){
    int b = blockIdx.y;
    int a = blockIdx.x*blockDim.x + threadIdx.x;
    int t = threadIdx.x;
    float o = 0.f;
    if (a < NA){
        float logit = pred[((size_t)b*NA + a)*PRED_DIM + 4];
        float tf = (g_amg[b*NA + a] > 0) ? 1.f : 0.f;
        o = bce_logits(logit, tf);
    }
    __shared__ float r0[256];
    r0[t] = o;
    __syncthreads();
    for (int s=128; s>=1; s>>=1){
        if (t < s) r0[t] += r0[t+s];
        __syncthreads();
    }
    if (t == 0) atomicAdd(&g_acc[b*4+0], r0[0]);
}

// ---------------- kernel 5: cls + box loss, warp per positive slot ----------------
__global__ void __launch_bounds__(256) posK(const float* __restrict__ pred,
                                            const float* __restrict__ tgt){
    int b = blockIdx.y;
    int warp = threadIdx.x >> 5, lane = threadIdx.x & 31;
    __shared__ float scls[NM];
    for (int i=threadIdx.x; i<NM; i+=blockDim.x) scls[i] = tgt[(b*NM+i)*5];
    __syncthreads();
    int nf = g_nf[b]; if (nf > MAXF) nf = MAXF;
    int slot = blockIdx.x*8 + warp;
    if (slot >= nf) return;
    int a = g_flist[b*MAXF + slot];
    int v = g_amg[b*NA + a];
    int cnt = v >> 16;
    if (cnt == 0) return;
    int mg;
    if (cnt == 1){
        mg = v & 0xffff;
    } else {
        // warp-parallel argmin over valid m (tie-break: lowest m == jnp.argmin)
        unsigned long long best = 0xFFFFFFFFFFFFFFFFull;
        for (int m = lane; m < NM; m += 32){
            if (scls[m] < 0.f) continue;
            float c = g_costc[((size_t)(b*NM+m))*MAXF + slot];
            unsigned long long key = ((unsigned long long)sortable_f(c) << 32) | (unsigned)m;
            if (key < best) best = key;
        }
        #pragma unroll
        for (int d=16; d>=1; d>>=1){
            unsigned long long o = __shfl_xor_sync(0xffffffffu, best, d);
            if (o < best) best = o;
        }
        mg = (int)(best & 0xFFFFFFFFull);
    }
    int gc = (int)fminf(fmaxf(scls[mg], 0.f), (float)(NC-1));
    const float* pr = pred + ((size_t)b*NA + a)*PRED_DIM;
    // cls BCE: lanes over classes (coalesced)
    float cl = bce_logits(pr[5+lane],    (lane==gc)    ?1.f:0.f)
             + bce_logits(pr[5+lane+32], (lane+32==gc) ?1.f:0.f);
    if (lane < 16)
        cl += bce_logits(pr[5+lane+64], (lane+64==gc) ?1.f:0.f);
    #pragma unroll
    for (int d=16; d>=1; d>>=1) cl += __shfl_xor_sync(0xffffffffu, cl, d);
    if (lane == 0){
        const float* tm = tgt + (b*NM+mg)*5;
        float gx=tm[1]*INPUT_SZ, gy=tm[2]*INPUT_SZ, gw=tm[3]*INPUT_SZ, gh=tm[4]*INPUT_SZ;
        float bx = ciou_loss(pr[0],pr[1],pr[2],pr[3], gx,gy,gw,gh);
        atomicAdd(&g_acc[b*4+1], cl);
        atomicAdd(&g_acc[b*4+2], bx);
        atomicAdd(&g_acc[b*4+3], 1.f);
    }
}

// ---------------- kernel 6: final reduction ----------------
__global__ void finalK(float* __restrict__ out){
    int t = threadIdx.x;
    float obj=0.f, cls=0.f, box=0.f, np=0.f;
    if (t < NB){
        np  = g_acc[t*4+3];
        obj = g_acc[t*4+0] / (float)NA;
        cls = (np > 0.f) ? g_acc[t*4+1]/(np*(float)NC) : 0.f;
        box = (np > 0.f) ? g_acc[t*4+2]/np : 0.f;
    }
    for (int s=16; s>=1; s>>=1){
        obj += __shfl_down_sync(0xffffffffu, obj, s);
        cls += __shfl_down_sync(0xffffffffu, cls, s);
        box += __shfl_down_sync(0xffffffffu, box, s);
        np  += __shfl_down_sync(0xffffffffu, np,  s);
    }
    if (t==0){
        float total = (5.f*box + obj + cls) / fmaxf(np, 1.f);
        out[0]=total; out[1]=box; out[2]=obj; out[3]=cls; out[4]=np;
    }
}

// ---------------- launch ----------------
extern "C" void kernel_launch(void* const* d_in, const int* in_sizes, int n_in,
                              void* d_out, int out_size){
    const float* pred = (const float*)d_in[0];   // [B, A, 85]
    const float* tgt  = (const float*)d_in[1];   // [B, M, 5]
    float* out = (float*)d_out;                  // 5 floats

    initK<<<(NB*NA/4 + 255)/256, 256>>>();
    markK<<<(NB*NM*3*36 + 255)/256, 256>>>(tgt);
    gatherK<<<dim3(MAXF/8, NB), 256>>>(pred);
    costK<<<dim3(NM, NB), 128>>>(tgt);
    dim3 gA((NA+255)/256, NB);
    lossK<<<gA, 256>>>(pred);
    posK<<<dim3(MAXF/8, NB), 256>>>(pred, tgt);
    finalK<<<1, 32>>>(out);
}